// round 1
// baseline (speedup 1.0000x reference)
#include <cuda_runtime.h>

#define Bc 128
#define Nc 256
#define Mc 1024
#define M4 (Mc/4)          // 256 float4 per row
#define ROWSTRIDE4 M4      // float4 stride between n rows
#define BSTRIDE4 (Nc*M4)   // 65536 float4 per batch

// Scratch (allocation-free per harness rules)
__device__ float g_dot[Bc*Nc];
__device__ float g_msq[Bc*Nc];

// ---------------------------------------------------------------------------
// Kernel 1: per-(b,n) dot(memory_row, k) and ||memory_row||^2.
// One warp per row, 8 float4 per lane, warp shuffle reduce.
// ---------------------------------------------------------------------------
__global__ void sim_kernel(const float4* __restrict__ mem,
                           const float4* __restrict__ k) {
    int warp = threadIdx.x >> 5;
    int lane = threadIdx.x & 31;
    int row  = blockIdx.x * 4 + warp;          // 0 .. B*N-1
    int b    = row >> 8;

    const float4* mr = mem + (size_t)row * M4;
    const float4* kr = k + b * M4;

    float dot = 0.f, msq = 0.f;
#pragma unroll
    for (int j = 0; j < 8; j++) {
        int i = lane + j * 32;
        float4 m4 = mr[i];
        float4 k4 = kr[i];
        dot += m4.x * k4.x + m4.y * k4.y + m4.z * k4.z + m4.w * k4.w;
        msq += m4.x * m4.x + m4.y * m4.y + m4.z * m4.z + m4.w * m4.w;
    }
#pragma unroll
    for (int o = 16; o > 0; o >>= 1) {
        dot += __shfl_xor_sync(0xFFFFFFFFu, dot, o);
        msq += __shfl_xor_sync(0xFFFFFFFFu, msq, o);
    }
    if (lane == 0) {
        g_dot[row] = dot;
        g_msq[row] = msq;
    }
}

// ---------------------------------------------------------------------------
// Block reductions (256 threads = 8 warps)
// ---------------------------------------------------------------------------
__device__ __forceinline__ float block_reduce_sum(float v, float* sm) {
#pragma unroll
    for (int o = 16; o > 0; o >>= 1) v += __shfl_xor_sync(0xFFFFFFFFu, v, o);
    int warp = threadIdx.x >> 5, lane = threadIdx.x & 31;
    if (lane == 0) sm[warp] = v;
    __syncthreads();
    if (warp == 0) {
        v = (lane < 8) ? sm[lane] : 0.f;
#pragma unroll
        for (int o = 4; o > 0; o >>= 1) v += __shfl_xor_sync(0xFFFFFFFFu, v, o);
        if (lane == 0) sm[0] = v;
    }
    __syncthreads();
    v = sm[0];
    __syncthreads();
    return v;
}

__device__ __forceinline__ float block_reduce_max(float v, float* sm) {
#pragma unroll
    for (int o = 16; o > 0; o >>= 1) v = fmaxf(v, __shfl_xor_sync(0xFFFFFFFFu, v, o));
    int warp = threadIdx.x >> 5, lane = threadIdx.x & 31;
    if (lane == 0) sm[warp] = v;
    __syncthreads();
    if (warp == 0) {
        v = (lane < 8) ? sm[lane] : -3.4e38f;
#pragma unroll
        for (int o = 4; o > 0; o >>= 1) v = fmaxf(v, __shfl_xor_sync(0xFFFFFFFFu, v, o));
        if (lane == 0) sm[0] = v;
    }
    __syncthreads();
    v = sm[0];
    __syncthreads();
    return v;
}

// ---------------------------------------------------------------------------
// Kernel 2: per-b weight pipeline. One block of 256 threads (thread = n).
// cosine -> softmax -> interpolate -> circular shift -> sharpen -> normalize
// ---------------------------------------------------------------------------
__global__ void weight_kernel(const float* __restrict__ k,
                              const float* __restrict__ beta,
                              const float* __restrict__ g,
                              const float* __restrict__ s,
                              const float* __restrict__ gamma,
                              const float* __restrict__ w_prev,
                              float* __restrict__ w_out) {
    int b = blockIdx.x;
    int n = threadIdx.x;

    __shared__ float sred[32];
    __shared__ float sw[Nc];

    // ||k_b|| : 256 threads x 4 elements
    const float* kb = k + b * Mc;
    float kq = 0.f;
#pragma unroll
    for (int j = 0; j < 4; j++) {
        float v = kb[n + j * 256];
        kq += v * v;
    }
    kq = block_reduce_sum(kq, sred);
    float knorm = fmaxf(sqrtf(kq), 1e-8f);

    float mnorm = fmaxf(sqrtf(g_msq[b * Nc + n]), 1e-8f);
    float cosv  = g_dot[b * Nc + n] / (mnorm * knorm);

    // softmax(beta * cos)
    float x    = beta[b] * cosv;
    float xmax = block_reduce_max(x, sred);
    float p    = expf(x - xmax);
    float psum = block_reduce_sum(p, sred);
    float wc   = p / psum;

    // interpolate
    float gg = g[b];
    float wg = gg * wc + (1.f - gg) * w_prev[b * Nc + n];
    sw[n] = wg;
    __syncthreads();

    // circular 3-tap shift: w_t[n] = s0*w[n-1] + s1*w[n] + s2*w[n+1]
    float s0 = s[b * 3 + 0], s1 = s[b * 3 + 1], s2 = s[b * 3 + 2];
    float wt = s0 * sw[(n + Nc - 1) & (Nc - 1)]
             + s1 * sw[n]
             + s2 * sw[(n + 1) & (Nc - 1)];

    // sharpen + normalize
    float wp   = powf(wt, gamma[b]);
    float wsum = block_reduce_sum(wp, sred);
    w_out[b * Nc + n] = wp / (wsum + 1e-16f);
}

// ---------------------------------------------------------------------------
// Kernel 3: erase/add write + read. Grid (4 m-chunks, B). 64 threads/block,
// one float4 column slice per thread. b reversed + n descending to hit
// L2 lines left warm by kernel 1 (LRU tail reuse).
// ---------------------------------------------------------------------------
__global__ void write_kernel(const float4* __restrict__ mem,
                             const float4* __restrict__ e,
                             const float4* __restrict__ a,
                             const float*  __restrict__ w,
                             float4* __restrict__ newmem,
                             float4* __restrict__ readout) {
    __shared__ float sw[Nc];
    int b     = (Bc - 1) - blockIdx.y;   // reversed batch order
    int chunk = blockIdx.x;              // 0..3
    int t     = threadIdx.x;             // 0..63

#pragma unroll
    for (int j = 0; j < 4; j++) sw[t + j * 64] = w[b * Nc + t + j * 64];

    int m4 = chunk * 64 + t;             // float4 index within row
    float4 e4 = e[b * M4 + m4];
    float4 a4 = a[b * M4 + m4];
    __syncthreads();

    const float4* mb = mem    + (size_t)b * BSTRIDE4 + m4;
    float4*       nb = newmem + (size_t)b * BSTRIDE4 + m4;

    float4 acc = make_float4(0.f, 0.f, 0.f, 0.f);

    // n descending, manual 4x unroll: 4 independent LDG.128 in flight
    for (int n0 = Nc - 4; n0 >= 0; n0 -= 4) {
        float4 v0 = mb[(n0 + 3) * ROWSTRIDE4];
        float4 v1 = mb[(n0 + 2) * ROWSTRIDE4];
        float4 v2 = mb[(n0 + 1) * ROWSTRIDE4];
        float4 v3 = mb[(n0 + 0) * ROWSTRIDE4];
        float w0 = sw[n0 + 3], w1 = sw[n0 + 2], w2 = sw[n0 + 1], w3 = sw[n0 + 0];

        float4 r;
        r.x = v0.x * (1.f - w0 * e4.x) + w0 * a4.x;
        r.y = v0.y * (1.f - w0 * e4.y) + w0 * a4.y;
        r.z = v0.z * (1.f - w0 * e4.z) + w0 * a4.z;
        r.w = v0.w * (1.f - w0 * e4.w) + w0 * a4.w;
        nb[(n0 + 3) * ROWSTRIDE4] = r;
        acc.x += w0 * r.x; acc.y += w0 * r.y; acc.z += w0 * r.z; acc.w += w0 * r.w;

        r.x = v1.x * (1.f - w1 * e4.x) + w1 * a4.x;
        r.y = v1.y * (1.f - w1 * e4.y) + w1 * a4.y;
        r.z = v1.z * (1.f - w1 * e4.z) + w1 * a4.z;
        r.w = v1.w * (1.f - w1 * e4.w) + w1 * a4.w;
        nb[(n0 + 2) * ROWSTRIDE4] = r;
        acc.x += w1 * r.x; acc.y += w1 * r.y; acc.z += w1 * r.z; acc.w += w1 * r.w;

        r.x = v2.x * (1.f - w2 * e4.x) + w2 * a4.x;
        r.y = v2.y * (1.f - w2 * e4.y) + w2 * a4.y;
        r.z = v2.z * (1.f - w2 * e4.z) + w2 * a4.z;
        r.w = v2.w * (1.f - w2 * e4.w) + w2 * a4.w;
        nb[(n0 + 1) * ROWSTRIDE4] = r;
        acc.x += w2 * r.x; acc.y += w2 * r.y; acc.z += w2 * r.z; acc.w += w2 * r.w;

        r.x = v3.x * (1.f - w3 * e4.x) + w3 * a4.x;
        r.y = v3.y * (1.f - w3 * e4.y) + w3 * a4.y;
        r.z = v3.z * (1.f - w3 * e4.z) + w3 * a4.z;
        r.w = v3.w * (1.f - w3 * e4.w) + w3 * a4.w;
        nb[(n0 + 0) * ROWSTRIDE4] = r;
        acc.x += w3 * r.x; acc.y += w3 * r.y; acc.z += w3 * r.z; acc.w += w3 * r.w;
    }

    readout[b * M4 + m4] = acc;
}

// ---------------------------------------------------------------------------
// Launch
// ---------------------------------------------------------------------------
extern "C" void kernel_launch(void* const* d_in, const int* in_sizes, int n_in,
                              void* d_out, int out_size) {
    const float* memory = (const float*)d_in[0];   // (B, N, M)
    const float* k      = (const float*)d_in[1];   // (B, M)
    const float* beta   = (const float*)d_in[2];   // (B, 1)
    const float* g      = (const float*)d_in[3];   // (B, 1)
    const float* s      = (const float*)d_in[4];   // (B, 3)
    const float* gamma  = (const float*)d_in[5];   // (B, 1)
    const float* w_prev = (const float*)d_in[6];   // (B, N)
    const float* e      = (const float*)d_in[7];   // (B, M)
    const float* a      = (const float*)d_in[8];   // (B, M)

    float* out      = (float*)d_out;
    float* out_read = out;                             // (B, M)
    float* out_mem  = out + Bc * Mc;                   // (B, N, M)
    float* out_w    = out + Bc * Mc + (size_t)Bc * Nc * Mc;  // (B, N)

    // Pass A: dots + norms (one warp per row, 4 warps/block)
    sim_kernel<<<(Bc * Nc) / 4, 128>>>((const float4*)memory, (const float4*)k);

    // Pass B: weights (tiny)
    weight_kernel<<<Bc, Nc>>>(k, beta, g, s, gamma, w_prev, out_w);

    // Pass C: erase/add/read, reversed for L2 tail reuse
    dim3 grid3(4, Bc);
    write_kernel<<<grid3, 64>>>((const float4*)memory, (const float4*)e,
                                (const float4*)a, out_w,
                                (float4*)out_mem, (float4*)out_read);
}

// round 2
// speedup vs baseline: 1.6278x; 1.6278x over previous
#include <cuda_runtime.h>

#define Bc 128
#define Nc 256
#define Mc 1024
#define M4 (Mc/4)          // 256 float4 per row
#define BSTRIDE4 (Nc*M4)   // float4 per batch
#define NSPLIT 8
#define NCHUNK (Nc/NSPLIT) // 32 rows per split

// Scratch (allocation-free per harness rules)
__device__ float g_dot[Bc*Nc];
__device__ float g_msq[Bc*Nc];
__device__ float4 g_part[NSPLIT * Bc * M4];   // 4 MB partial read sums

// ---------------------------------------------------------------------------
// Kernel 1: per-(b,n) dot(memory_row, k) and ||memory_row||^2.
// One warp per row, 8 warps per block.
// ---------------------------------------------------------------------------
__global__ void sim_kernel(const float4* __restrict__ mem,
                           const float4* __restrict__ k) {
    int warp = threadIdx.x >> 5;
    int lane = threadIdx.x & 31;
    int row  = blockIdx.x * 8 + warp;          // 0 .. B*N-1
    int b    = row >> 8;

    const float4* mr = mem + (size_t)row * M4;
    const float4* kr = k + b * M4;

    float dot = 0.f, msq = 0.f;
#pragma unroll
    for (int j = 0; j < 8; j++) {
        int i = lane + j * 32;
        float4 m4 = mr[i];
        float4 k4 = kr[i];
        dot += m4.x * k4.x + m4.y * k4.y + m4.z * k4.z + m4.w * k4.w;
        msq += m4.x * m4.x + m4.y * m4.y + m4.z * m4.z + m4.w * m4.w;
    }
#pragma unroll
    for (int o = 16; o > 0; o >>= 1) {
        dot += __shfl_xor_sync(0xFFFFFFFFu, dot, o);
        msq += __shfl_xor_sync(0xFFFFFFFFu, msq, o);
    }
    if (lane == 0) {
        g_dot[row] = dot;
        g_msq[row] = msq;
    }
}

// ---------------------------------------------------------------------------
// Block reductions (256 threads = 8 warps)
// ---------------------------------------------------------------------------
__device__ __forceinline__ float block_reduce_sum(float v, float* sm) {
#pragma unroll
    for (int o = 16; o > 0; o >>= 1) v += __shfl_xor_sync(0xFFFFFFFFu, v, o);
    int warp = threadIdx.x >> 5, lane = threadIdx.x & 31;
    if (lane == 0) sm[warp] = v;
    __syncthreads();
    if (warp == 0) {
        v = (lane < 8) ? sm[lane] : 0.f;
#pragma unroll
        for (int o = 4; o > 0; o >>= 1) v += __shfl_xor_sync(0xFFFFFFFFu, v, o);
        if (lane == 0) sm[0] = v;
    }
    __syncthreads();
    v = sm[0];
    __syncthreads();
    return v;
}

__device__ __forceinline__ float block_reduce_max(float v, float* sm) {
#pragma unroll
    for (int o = 16; o > 0; o >>= 1) v = fmaxf(v, __shfl_xor_sync(0xFFFFFFFFu, v, o));
    int warp = threadIdx.x >> 5, lane = threadIdx.x & 31;
    if (lane == 0) sm[warp] = v;
    __syncthreads();
    if (warp == 0) {
        v = (lane < 8) ? sm[lane] : -3.4e38f;
#pragma unroll
        for (int o = 4; o > 0; o >>= 1) v = fmaxf(v, __shfl_xor_sync(0xFFFFFFFFu, v, o));
        if (lane == 0) sm[0] = v;
    }
    __syncthreads();
    v = sm[0];
    __syncthreads();
    return v;
}

// ---------------------------------------------------------------------------
// Kernel 2: per-b weight pipeline. One block of 256 threads (thread = n).
// ---------------------------------------------------------------------------
__global__ void weight_kernel(const float* __restrict__ k,
                              const float* __restrict__ beta,
                              const float* __restrict__ g,
                              const float* __restrict__ s,
                              const float* __restrict__ gamma,
                              const float* __restrict__ w_prev,
                              float* __restrict__ w_out) {
    int b = blockIdx.x;
    int n = threadIdx.x;

    __shared__ float sred[32];
    __shared__ float sw[Nc];

    const float* kb = k + b * Mc;
    float kq = 0.f;
#pragma unroll
    for (int j = 0; j < 4; j++) {
        float v = kb[n + j * 256];
        kq += v * v;
    }
    kq = block_reduce_sum(kq, sred);
    float knorm = fmaxf(sqrtf(kq), 1e-8f);

    float mnorm = fmaxf(sqrtf(g_msq[b * Nc + n]), 1e-8f);
    float cosv  = g_dot[b * Nc + n] / (mnorm * knorm);

    float x    = beta[b] * cosv;
    float xmax = block_reduce_max(x, sred);
    float p    = expf(x - xmax);
    float psum = block_reduce_sum(p, sred);
    float wc   = p / psum;

    float gg = g[b];
    float wg = gg * wc + (1.f - gg) * w_prev[b * Nc + n];
    sw[n] = wg;
    __syncthreads();

    float s0 = s[b * 3 + 0], s1 = s[b * 3 + 1], s2 = s[b * 3 + 2];
    float wt = s0 * sw[(n + Nc - 1) & (Nc - 1)]
             + s1 * sw[n]
             + s2 * sw[(n + 1) & (Nc - 1)];

    float wp   = powf(wt, gamma[b]);
    float wsum = block_reduce_sum(wp, sred);
    w_out[b * Nc + n] = wp / (wsum + 1e-16f);
}

// ---------------------------------------------------------------------------
// Kernel 3: erase/add write + partial read. Grid (NSPLIT, B), 256 threads.
// Thread t owns float4 column t; each block covers NCHUNK=32 rows.
// ---------------------------------------------------------------------------
__global__ void write_kernel(const float4* __restrict__ mem,
                             const float4* __restrict__ e,
                             const float4* __restrict__ a,
                             const float*  __restrict__ w,
                             float4* __restrict__ newmem) {
    __shared__ float sw[NCHUNK];
    int sp = blockIdx.x;                 // 0..NSPLIT-1
    int b  = (Bc - 1) - blockIdx.y;      // reversed batch order (L2 tail reuse)
    int t  = threadIdx.x;                // 0..255
    int nbase = sp * NCHUNK;

    if (t < NCHUNK) sw[t] = w[b * Nc + nbase + t];

    float4 e4 = e[b * M4 + t];
    float4 a4 = a[b * M4 + t];
    __syncthreads();

    const float4* mb = mem    + (size_t)b * BSTRIDE4 + (size_t)nbase * M4 + t;
    float4*       nb = newmem + (size_t)b * BSTRIDE4 + (size_t)nbase * M4 + t;

    float4 acc = make_float4(0.f, 0.f, 0.f, 0.f);

#pragma unroll 2
    for (int n0 = NCHUNK - 4; n0 >= 0; n0 -= 4) {
        float4 v0 = mb[(n0 + 3) * M4];
        float4 v1 = mb[(n0 + 2) * M4];
        float4 v2 = mb[(n0 + 1) * M4];
        float4 v3 = mb[(n0 + 0) * M4];
        float w0 = sw[n0 + 3], w1 = sw[n0 + 2], w2 = sw[n0 + 1], w3 = sw[n0 + 0];

        float4 r;
        r.x = v0.x * (1.f - w0 * e4.x) + w0 * a4.x;
        r.y = v0.y * (1.f - w0 * e4.y) + w0 * a4.y;
        r.z = v0.z * (1.f - w0 * e4.z) + w0 * a4.z;
        r.w = v0.w * (1.f - w0 * e4.w) + w0 * a4.w;
        nb[(n0 + 3) * M4] = r;
        acc.x += w0 * r.x; acc.y += w0 * r.y; acc.z += w0 * r.z; acc.w += w0 * r.w;

        r.x = v1.x * (1.f - w1 * e4.x) + w1 * a4.x;
        r.y = v1.y * (1.f - w1 * e4.y) + w1 * a4.y;
        r.z = v1.z * (1.f - w1 * e4.z) + w1 * a4.z;
        r.w = v1.w * (1.f - w1 * e4.w) + w1 * a4.w;
        nb[(n0 + 2) * M4] = r;
        acc.x += w1 * r.x; acc.y += w1 * r.y; acc.z += w1 * r.z; acc.w += w1 * r.w;

        r.x = v2.x * (1.f - w2 * e4.x) + w2 * a4.x;
        r.y = v2.y * (1.f - w2 * e4.y) + w2 * a4.y;
        r.z = v2.z * (1.f - w2 * e4.z) + w2 * a4.z;
        r.w = v2.w * (1.f - w2 * e4.w) + w2 * a4.w;
        nb[(n0 + 1) * M4] = r;
        acc.x += w2 * r.x; acc.y += w2 * r.y; acc.z += w2 * r.z; acc.w += w2 * r.w;

        r.x = v3.x * (1.f - w3 * e4.x) + w3 * a4.x;
        r.y = v3.y * (1.f - w3 * e4.y) + w3 * a4.y;
        r.z = v3.z * (1.f - w3 * e4.z) + w3 * a4.z;
        r.w = v3.w * (1.f - w3 * e4.w) + w3 * a4.w;
        nb[(n0 + 0) * M4] = r;
        acc.x += w3 * r.x; acc.y += w3 * r.y; acc.z += w3 * r.z; acc.w += w3 * r.w;
    }

    g_part[(sp * Bc + b) * M4 + t] = acc;
}

// ---------------------------------------------------------------------------
// Kernel 4: fold NSPLIT partial read sums (deterministic order).
// ---------------------------------------------------------------------------
__global__ void reduce_kernel(float4* __restrict__ readout) {
    int i = blockIdx.x * blockDim.x + threadIdx.x;   // 0 .. B*M4-1
    float4 acc = make_float4(0.f, 0.f, 0.f, 0.f);
#pragma unroll
    for (int sp = 0; sp < NSPLIT; sp++) {
        float4 p = g_part[sp * Bc * M4 + i];
        acc.x += p.x; acc.y += p.y; acc.z += p.z; acc.w += p.w;
    }
    readout[i] = acc;
}

// ---------------------------------------------------------------------------
// Launch
// ---------------------------------------------------------------------------
extern "C" void kernel_launch(void* const* d_in, const int* in_sizes, int n_in,
                              void* d_out, int out_size) {
    const float* memory = (const float*)d_in[0];   // (B, N, M)
    const float* k      = (const float*)d_in[1];   // (B, M)
    const float* beta   = (const float*)d_in[2];   // (B, 1)
    const float* g      = (const float*)d_in[3];   // (B, 1)
    const float* s      = (const float*)d_in[4];   // (B, 3)
    const float* gamma  = (const float*)d_in[5];   // (B, 1)
    const float* w_prev = (const float*)d_in[6];   // (B, N)
    const float* e      = (const float*)d_in[7];   // (B, M)
    const float* a      = (const float*)d_in[8];   // (B, M)

    float* out      = (float*)d_out;
    float* out_read = out;                             // (B, M)
    float* out_mem  = out + Bc * Mc;                   // (B, N, M)
    float* out_w    = out + Bc * Mc + (size_t)Bc * Nc * Mc;  // (B, N)

    // Pass A: dots + norms (one warp per row, 8 warps/block)
    sim_kernel<<<(Bc * Nc) / 8, 256>>>((const float4*)memory, (const float4*)k);

    // Pass B: weights (tiny)
    weight_kernel<<<Bc, Nc>>>(k, beta, g, s, gamma, w_prev, out_w);

    // Pass C: erase/add + partial read, split over N for MLP
    dim3 grid3(NSPLIT, Bc);
    write_kernel<<<grid3, 256>>>((const float4*)memory, (const float4*)e,
                                 (const float4*)a, out_w,
                                 (float4*)out_mem);

    // Pass D: fold partials into read output
    reduce_kernel<<<(Bc * M4) / 256, 256>>>((float4*)out_read);
}

// round 3
// speedup vs baseline: 1.6798x; 1.0319x over previous
#include <cuda_runtime.h>

#define Bc 128
#define Nc 256
#define Mc 1024
#define M4 (Mc/4)          // 256 float4 per row
#define BSTRIDE4 (Nc*M4)   // float4 per batch
#define NSPLIT 8
#define NCHUNK (Nc/NSPLIT) // 32 rows per split

// Scratch (allocation-free per harness rules)
__device__ float g_dot[Bc*Nc];
__device__ float g_msq[Bc*Nc];
__device__ float4 g_part[NSPLIT * Bc * M4];   // 4 MB partial read sums

// ---------------------------------------------------------------------------
// Kernel 1: per-(b,n) dot(memory_row, k) and ||memory_row||^2.
// One warp per TWO rows (n and n+128 of the same b): shared k loads,
// 16 outstanding memory LDG.128 per lane group for MLP.
// ---------------------------------------------------------------------------
__global__ void sim_kernel(const float4* __restrict__ mem,
                           const float4* __restrict__ k) {
    int warp = threadIdx.x >> 5;
    int lane = threadIdx.x & 31;
    int pair = blockIdx.x * 8 + warp;          // 0 .. B*N/2-1
    int b    = pair >> 7;                      // 128 pairs per batch
    int n    = pair & 127;
    int row0 = b * Nc + n;
    int row1 = row0 + 128;

    const float4* m0 = mem + (size_t)row0 * M4;
    const float4* m1 = mem + (size_t)row1 * M4;
    const float4* kr = k + b * M4;

    float d0 = 0.f, q0 = 0.f, d1 = 0.f, q1 = 0.f;
#pragma unroll
    for (int j = 0; j < 8; j++) {
        int i = lane + j * 32;
        float4 k4 = kr[i];
        float4 a4 = m0[i];
        float4 b4 = m1[i];
        d0 += a4.x * k4.x + a4.y * k4.y + a4.z * k4.z + a4.w * k4.w;
        q0 += a4.x * a4.x + a4.y * a4.y + a4.z * a4.z + a4.w * a4.w;
        d1 += b4.x * k4.x + b4.y * k4.y + b4.z * k4.z + b4.w * k4.w;
        q1 += b4.x * b4.x + b4.y * b4.y + b4.z * b4.z + b4.w * b4.w;
    }
#pragma unroll
    for (int o = 16; o > 0; o >>= 1) {
        d0 += __shfl_xor_sync(0xFFFFFFFFu, d0, o);
        q0 += __shfl_xor_sync(0xFFFFFFFFu, q0, o);
        d1 += __shfl_xor_sync(0xFFFFFFFFu, d1, o);
        q1 += __shfl_xor_sync(0xFFFFFFFFu, q1, o);
    }
    if (lane == 0) {
        g_dot[row0] = d0;
        g_msq[row0] = q0;
        g_dot[row1] = d1;
        g_msq[row1] = q1;
    }
}

// ---------------------------------------------------------------------------
// Block reductions (256 threads = 8 warps)
// ---------------------------------------------------------------------------
__device__ __forceinline__ float block_reduce_sum(float v, float* sm) {
#pragma unroll
    for (int o = 16; o > 0; o >>= 1) v += __shfl_xor_sync(0xFFFFFFFFu, v, o);
    int warp = threadIdx.x >> 5, lane = threadIdx.x & 31;
    if (lane == 0) sm[warp] = v;
    __syncthreads();
    if (warp == 0) {
        v = (lane < 8) ? sm[lane] : 0.f;
#pragma unroll
        for (int o = 4; o > 0; o >>= 1) v += __shfl_xor_sync(0xFFFFFFFFu, v, o);
        if (lane == 0) sm[0] = v;
    }
    __syncthreads();
    v = sm[0];
    __syncthreads();
    return v;
}

__device__ __forceinline__ float block_reduce_max(float v, float* sm) {
#pragma unroll
    for (int o = 16; o > 0; o >>= 1) v = fmaxf(v, __shfl_xor_sync(0xFFFFFFFFu, v, o));
    int warp = threadIdx.x >> 5, lane = threadIdx.x & 31;
    if (lane == 0) sm[warp] = v;
    __syncthreads();
    if (warp == 0) {
        v = (lane < 8) ? sm[lane] : -3.4e38f;
#pragma unroll
        for (int o = 4; o > 0; o >>= 1) v = fmaxf(v, __shfl_xor_sync(0xFFFFFFFFu, v, o));
        if (lane == 0) sm[0] = v;
    }
    __syncthreads();
    v = sm[0];
    __syncthreads();
    return v;
}

// ---------------------------------------------------------------------------
// Kernel 2: per-b weight pipeline. One block of 256 threads (thread = n).
// ---------------------------------------------------------------------------
__global__ void weight_kernel(const float* __restrict__ k,
                              const float* __restrict__ beta,
                              const float* __restrict__ g,
                              const float* __restrict__ s,
                              const float* __restrict__ gamma,
                              const float* __restrict__ w_prev,
                              float* __restrict__ w_out) {
    int b = blockIdx.x;
    int n = threadIdx.x;

    __shared__ float sred[32];
    __shared__ float sw[Nc];

    const float* kb = k + b * Mc;
    float kq = 0.f;
#pragma unroll
    for (int j = 0; j < 4; j++) {
        float v = kb[n + j * 256];
        kq += v * v;
    }
    kq = block_reduce_sum(kq, sred);
    float knorm = fmaxf(sqrtf(kq), 1e-8f);

    float mnorm = fmaxf(sqrtf(g_msq[b * Nc + n]), 1e-8f);
    float cosv  = g_dot[b * Nc + n] / (mnorm * knorm);

    float x    = beta[b] * cosv;
    float xmax = block_reduce_max(x, sred);
    float p    = expf(x - xmax);
    float psum = block_reduce_sum(p, sred);
    float wc   = p / psum;

    float gg = g[b];
    float wg = gg * wc + (1.f - gg) * w_prev[b * Nc + n];
    sw[n] = wg;
    __syncthreads();

    float s0 = s[b * 3 + 0], s1 = s[b * 3 + 1], s2 = s[b * 3 + 2];
    float wt = s0 * sw[(n + Nc - 1) & (Nc - 1)]
             + s1 * sw[n]
             + s2 * sw[(n + 1) & (Nc - 1)];

    float wp   = powf(wt, gamma[b]);
    float wsum = block_reduce_sum(wp, sred);
    w_out[b * Nc + n] = wp / (wsum + 1e-16f);
}

// ---------------------------------------------------------------------------
// Kernel 3: erase/add write + partial read. Grid (NSPLIT, B), 256 threads.
// Thread t owns float4 column t; each block covers NCHUNK=32 rows.
// ---------------------------------------------------------------------------
__global__ void write_kernel(const float4* __restrict__ mem,
                             const float4* __restrict__ e,
                             const float4* __restrict__ a,
                             const float*  __restrict__ w,
                             float4* __restrict__ newmem) {
    __shared__ float sw[NCHUNK];
    int sp = blockIdx.x;                 // 0..NSPLIT-1
    int b  = (Bc - 1) - blockIdx.y;      // reversed batch order (L2 tail reuse)
    int t  = threadIdx.x;                // 0..255
    int nbase = sp * NCHUNK;

    if (t < NCHUNK) sw[t] = w[b * Nc + nbase + t];

    float4 e4 = e[b * M4 + t];
    float4 a4 = a[b * M4 + t];
    __syncthreads();

    const float4* mb = mem    + (size_t)b * BSTRIDE4 + (size_t)nbase * M4 + t;
    float4*       nb = newmem + (size_t)b * BSTRIDE4 + (size_t)nbase * M4 + t;

    float4 acc = make_float4(0.f, 0.f, 0.f, 0.f);

#pragma unroll 2
    for (int n0 = NCHUNK - 4; n0 >= 0; n0 -= 4) {
        float4 v0 = mb[(n0 + 3) * M4];
        float4 v1 = mb[(n0 + 2) * M4];
        float4 v2 = mb[(n0 + 1) * M4];
        float4 v3 = mb[(n0 + 0) * M4];
        float w0 = sw[n0 + 3], w1 = sw[n0 + 2], w2 = sw[n0 + 1], w3 = sw[n0 + 0];

        float4 r;
        r.x = v0.x * (1.f - w0 * e4.x) + w0 * a4.x;
        r.y = v0.y * (1.f - w0 * e4.y) + w0 * a4.y;
        r.z = v0.z * (1.f - w0 * e4.z) + w0 * a4.z;
        r.w = v0.w * (1.f - w0 * e4.w) + w0 * a4.w;
        nb[(n0 + 3) * M4] = r;
        acc.x += w0 * r.x; acc.y += w0 * r.y; acc.z += w0 * r.z; acc.w += w0 * r.w;

        r.x = v1.x * (1.f - w1 * e4.x) + w1 * a4.x;
        r.y = v1.y * (1.f - w1 * e4.y) + w1 * a4.y;
        r.z = v1.z * (1.f - w1 * e4.z) + w1 * a4.z;
        r.w = v1.w * (1.f - w1 * e4.w) + w1 * a4.w;
        nb[(n0 + 2) * M4] = r;
        acc.x += w1 * r.x; acc.y += w1 * r.y; acc.z += w1 * r.z; acc.w += w1 * r.w;

        r.x = v2.x * (1.f - w2 * e4.x) + w2 * a4.x;
        r.y = v2.y * (1.f - w2 * e4.y) + w2 * a4.y;
        r.z = v2.z * (1.f - w2 * e4.z) + w2 * a4.z;
        r.w = v2.w * (1.f - w2 * e4.w) + w2 * a4.w;
        nb[(n0 + 1) * M4] = r;
        acc.x += w2 * r.x; acc.y += w2 * r.y; acc.z += w2 * r.z; acc.w += w2 * r.w;

        r.x = v3.x * (1.f - w3 * e4.x) + w3 * a4.x;
        r.y = v3.y * (1.f - w3 * e4.y) + w3 * a4.y;
        r.z = v3.z * (1.f - w3 * e4.z) + w3 * a4.z;
        r.w = v3.w * (1.f - w3 * e4.w) + w3 * a4.w;
        nb[(n0 + 0) * M4] = r;
        acc.x += w3 * r.x; acc.y += w3 * r.y; acc.z += w3 * r.z; acc.w += w3 * r.w;
    }

    g_part[(sp * Bc + b) * M4 + t] = acc;
}

// ---------------------------------------------------------------------------
// Kernel 4: fold NSPLIT partial read sums. Scalar granularity for 4x the
// warps (latency-bound at float4 granularity). Same deterministic order.
// ---------------------------------------------------------------------------
__global__ void reduce_kernel(float* __restrict__ readout) {
    int i = blockIdx.x * blockDim.x + threadIdx.x;   // 0 .. B*M-1
    const float* gp = (const float*)g_part;
    float acc = 0.f;
#pragma unroll
    for (int sp = 0; sp < NSPLIT; sp++) {
        acc += gp[sp * Bc * Mc + i];
    }
    readout[i] = acc;
}

// ---------------------------------------------------------------------------
// Launch
// ---------------------------------------------------------------------------
extern "C" void kernel_launch(void* const* d_in, const int* in_sizes, int n_in,
                              void* d_out, int out_size) {
    const float* memory = (const float*)d_in[0];   // (B, N, M)
    const float* k      = (const float*)d_in[1];   // (B, M)
    const float* beta   = (const float*)d_in[2];   // (B, 1)
    const float* g      = (const float*)d_in[3];   // (B, 1)
    const float* s      = (const float*)d_in[4];   // (B, 3)
    const float* gamma  = (const float*)d_in[5];   // (B, 1)
    const float* w_prev = (const float*)d_in[6];   // (B, N)
    const float* e      = (const float*)d_in[7];   // (B, M)
    const float* a      = (const float*)d_in[8];   // (B, M)

    float* out      = (float*)d_out;
    float* out_read = out;                             // (B, M)
    float* out_mem  = out + Bc * Mc;                   // (B, N, M)
    float* out_w    = out + Bc * Mc + (size_t)Bc * Nc * Mc;  // (B, N)

    // Pass A: dots + norms (one warp per row-pair, 8 warps/block)
    sim_kernel<<<(Bc * Nc) / 16, 256>>>((const float4*)memory, (const float4*)k);

    // Pass B: weights (tiny)
    weight_kernel<<<Bc, Nc>>>(k, beta, g, s, gamma, w_prev, out_w);

    // Pass C: erase/add + partial read, split over N for MLP
    dim3 grid3(NSPLIT, Bc);
    write_kernel<<<grid3, 256>>>((const float4*)memory, (const float4*)e,
                                 (const float4*)a, out_w,
                                 (float4*)out_mem);

    // Pass D: fold partials into read output (scalar, 512 blocks)
    reduce_kernel<<<(Bc * Mc) / 256, 256>>>(out_read);
}

// round 7
// speedup vs baseline: 1.7281x; 1.0287x over previous
#include <cuda_runtime.h>

#define Bc 128
#define Nc 256
#define Mc 1024
#define M4 (Mc/4)          // 256 float4 per row
#define BSTRIDE4 (Nc*M4)   // float4 per batch
#define NSPLIT 8
#define NCHUNK (Nc/NSPLIT) // 32 rows per split

// Scratch (allocation-free per harness rules)
__device__ float g_dot[Bc*Nc];
__device__ float g_msq[Bc*Nc];

// ---------------------------------------------------------------------------
// Kernel 1: per-(b,n) dot(memory_row, k) and ||memory_row||^2.
// One warp per TWO rows (n and n+128 of the same b): shared k loads,
// 16 outstanding memory LDG.128 per warp for MLP.
// ---------------------------------------------------------------------------
__global__ void sim_kernel(const float4* __restrict__ mem,
                           const float4* __restrict__ k) {
    int warp = threadIdx.x >> 5;
    int lane = threadIdx.x & 31;
    int pair = blockIdx.x * 8 + warp;          // 0 .. B*N/2-1
    int b    = pair >> 7;                      // 128 pairs per batch
    int n    = pair & 127;
    int row0 = b * Nc + n;
    int row1 = row0 + 128;

    const float4* m0 = mem + (size_t)row0 * M4;
    const float4* m1 = mem + (size_t)row1 * M4;
    const float4* kr = k + b * M4;

    float d0 = 0.f, q0 = 0.f, d1 = 0.f, q1 = 0.f;
#pragma unroll
    for (int j = 0; j < 8; j++) {
        int i = lane + j * 32;
        float4 k4 = kr[i];
        float4 a4 = m0[i];
        float4 b4 = m1[i];
        d0 += a4.x * k4.x + a4.y * k4.y + a4.z * k4.z + a4.w * k4.w;
        q0 += a4.x * a4.x + a4.y * a4.y + a4.z * a4.z + a4.w * a4.w;
        d1 += b4.x * k4.x + b4.y * k4.y + b4.z * k4.z + b4.w * k4.w;
        q1 += b4.x * b4.x + b4.y * b4.y + b4.z * b4.z + b4.w * b4.w;
    }
#pragma unroll
    for (int o = 16; o > 0; o >>= 1) {
        d0 += __shfl_xor_sync(0xFFFFFFFFu, d0, o);
        q0 += __shfl_xor_sync(0xFFFFFFFFu, q0, o);
        d1 += __shfl_xor_sync(0xFFFFFFFFu, d1, o);
        q1 += __shfl_xor_sync(0xFFFFFFFFu, q1, o);
    }
    if (lane == 0) {
        g_dot[row0] = d0;
        g_msq[row0] = q0;
        g_dot[row1] = d1;
        g_msq[row1] = q1;
    }
}

// ---------------------------------------------------------------------------
// Block reductions (256 threads = 8 warps)
// ---------------------------------------------------------------------------
__device__ __forceinline__ float block_reduce_sum(float v, float* sm) {
#pragma unroll
    for (int o = 16; o > 0; o >>= 1) v += __shfl_xor_sync(0xFFFFFFFFu, v, o);
    int warp = threadIdx.x >> 5, lane = threadIdx.x & 31;
    if (lane == 0) sm[warp] = v;
    __syncthreads();
    if (warp == 0) {
        v = (lane < 8) ? sm[lane] : 0.f;
#pragma unroll
        for (int o = 4; o > 0; o >>= 1) v += __shfl_xor_sync(0xFFFFFFFFu, v, o);
        if (lane == 0) sm[0] = v;
    }
    __syncthreads();
    v = sm[0];
    __syncthreads();
    return v;
}

__device__ __forceinline__ float block_reduce_max(float v, float* sm) {
#pragma unroll
    for (int o = 16; o > 0; o >>= 1) v = fmaxf(v, __shfl_xor_sync(0xFFFFFFFFu, v, o));
    int warp = threadIdx.x >> 5, lane = threadIdx.x & 31;
    if (lane == 0) sm[warp] = v;
    __syncthreads();
    if (warp == 0) {
        v = (lane < 8) ? sm[lane] : -3.4e38f;
#pragma unroll
        for (int o = 4; o > 0; o >>= 1) v = fmaxf(v, __shfl_xor_sync(0xFFFFFFFFu, v, o));
        if (lane == 0) sm[0] = v;
    }
    __syncthreads();
    v = sm[0];
    __syncthreads();
    return v;
}

// ---------------------------------------------------------------------------
// Kernel 2: per-b weight pipeline + zero-init of the read output for this b
// (write_kernel accumulates into it atomically afterwards).
// ---------------------------------------------------------------------------
__global__ void weight_kernel(const float* __restrict__ k,
                              const float* __restrict__ beta,
                              const float* __restrict__ g,
                              const float* __restrict__ s,
                              const float* __restrict__ gamma,
                              const float* __restrict__ w_prev,
                              float* __restrict__ w_out,
                              float4* __restrict__ read_out) {
    int b = blockIdx.x;
    int n = threadIdx.x;

    // zero the read accumulator for this batch (1 float4 per thread)
    read_out[b * M4 + n] = make_float4(0.f, 0.f, 0.f, 0.f);

    __shared__ float sred[32];
    __shared__ float sw[Nc];

    const float* kb = k + b * Mc;
    float kq = 0.f;
#pragma unroll
    for (int j = 0; j < 4; j++) {
        float v = kb[n + j * 256];
        kq += v * v;
    }
    kq = block_reduce_sum(kq, sred);
    float knorm = fmaxf(sqrtf(kq), 1e-8f);

    float mnorm = fmaxf(sqrtf(g_msq[b * Nc + n]), 1e-8f);
    float cosv  = g_dot[b * Nc + n] / (mnorm * knorm);

    float x    = beta[b] * cosv;
    float xmax = block_reduce_max(x, sred);
    float p    = expf(x - xmax);
    float psum = block_reduce_sum(p, sred);
    float wc   = p / psum;

    float gg = g[b];
    float wg = gg * wc + (1.f - gg) * w_prev[b * Nc + n];
    sw[n] = wg;
    __syncthreads();

    float s0 = s[b * 3 + 0], s1 = s[b * 3 + 1], s2 = s[b * 3 + 2];
    float wt = s0 * sw[(n + Nc - 1) & (Nc - 1)]
             + s1 * sw[n]
             + s2 * sw[(n + 1) & (Nc - 1)];

    float wp   = powf(wt, gamma[b]);
    float wsum = block_reduce_sum(wp, sred);
    w_out[b * Nc + n] = wp / (wsum + 1e-16f);
}

// ---------------------------------------------------------------------------
// Kernel 3: erase/add write + read accumulation. Grid (NSPLIT, B), 256 thr.
// Thread t owns float4 column t; each block covers NCHUNK=32 rows.
// Read partial goes straight to out_read via REDG atomics (8 contributors
// per address, spread addresses -> negligible vs the 276 MB stream).
// ---------------------------------------------------------------------------
__global__ void write_kernel(const float4* __restrict__ mem,
                             const float4* __restrict__ e,
                             const float4* __restrict__ a,
                             const float*  __restrict__ w,
                             float4* __restrict__ newmem,
                             float* __restrict__ read_out) {
    __shared__ float sw[NCHUNK];
    int sp = blockIdx.x;                 // 0..NSPLIT-1
    int b  = (Bc - 1) - blockIdx.y;      // reversed batch order (L2 tail reuse)
    int t  = threadIdx.x;                // 0..255
    int nbase = sp * NCHUNK;

    if (t < NCHUNK) sw[t] = w[b * Nc + nbase + t];

    float4 e4 = e[b * M4 + t];
    float4 a4 = a[b * M4 + t];
    __syncthreads();

    const float4* mb = mem    + (size_t)b * BSTRIDE4 + (size_t)nbase * M4 + t;
    float4*       nb = newmem + (size_t)b * BSTRIDE4 + (size_t)nbase * M4 + t;

    float4 acc = make_float4(0.f, 0.f, 0.f, 0.f);

#pragma unroll 2
    for (int n0 = NCHUNK - 4; n0 >= 0; n0 -= 4) {
        float4 v0 = mb[(n0 + 3) * M4];
        float4 v1 = mb[(n0 + 2) * M4];
        float4 v2 = mb[(n0 + 1) * M4];
        float4 v3 = mb[(n0 + 0) * M4];
        float w0 = sw[n0 + 3], w1 = sw[n0 + 2], w2 = sw[n0 + 1], w3 = sw[n0 + 0];

        float4 r;
        r.x = v0.x * (1.f - w0 * e4.x) + w0 * a4.x;
        r.y = v0.y * (1.f - w0 * e4.y) + w0 * a4.y;
        r.z = v0.z * (1.f - w0 * e4.z) + w0 * a4.z;
        r.w = v0.w * (1.f - w0 * e4.w) + w0 * a4.w;
        nb[(n0 + 3) * M4] = r;
        acc.x += w0 * r.x; acc.y += w0 * r.y; acc.z += w0 * r.z; acc.w += w0 * r.w;

        r.x = v1.x * (1.f - w1 * e4.x) + w1 * a4.x;
        r.y = v1.y * (1.f - w1 * e4.y) + w1 * a4.y;
        r.z = v1.z * (1.f - w1 * e4.z) + w1 * a4.z;
        r.w = v1.w * (1.f - w1 * e4.w) + w1 * a4.w;
        nb[(n0 + 2) * M4] = r;
        acc.x += w1 * r.x; acc.y += w1 * r.y; acc.z += w1 * r.z; acc.w += w1 * r.w;

        r.x = v2.x * (1.f - w2 * e4.x) + w2 * a4.x;
        r.y = v2.y * (1.f - w2 * e4.y) + w2 * a4.y;
        r.z = v2.z * (1.f - w2 * e4.z) + w2 * a4.z;
        r.w = v2.w * (1.f - w2 * e4.w) + w2 * a4.w;
        nb[(n0 + 1) * M4] = r;
        acc.x += w2 * r.x; acc.y += w2 * r.y; acc.z += w2 * r.z; acc.w += w2 * r.w;

        r.x = v3.x * (1.f - w3 * e4.x) + w3 * a4.x;
        r.y = v3.y * (1.f - w3 * e4.y) + w3 * a4.y;
        r.z = v3.z * (1.f - w3 * e4.z) + w3 * a4.z;
        r.w = v3.w * (1.f - w3 * e4.w) + w3 * a4.w;
        nb[(n0 + 0) * M4] = r;
        acc.x += w3 * r.x; acc.y += w3 * r.y; acc.z += w3 * r.z; acc.w += w3 * r.w;
    }

    float* ro = read_out + b * Mc + t * 4;
    atomicAdd(ro + 0, acc.x);
    atomicAdd(ro + 1, acc.y);
    atomicAdd(ro + 2, acc.z);
    atomicAdd(ro + 3, acc.w);
}

// ---------------------------------------------------------------------------
// Launch
// ---------------------------------------------------------------------------
extern "C" void kernel_launch(void* const* d_in, const int* in_sizes, int n_in,
                              void* d_out, int out_size) {
    const float* memory = (const float*)d_in[0];   // (B, N, M)
    const float* k      = (const float*)d_in[1];   // (B, M)
    const float* beta   = (const float*)d_in[2];   // (B, 1)
    const float* g      = (const float*)d_in[3];   // (B, 1)
    const float* s      = (const float*)d_in[4];   // (B, 3)
    const float* gamma  = (const float*)d_in[5];   // (B, 1)
    const float* w_prev = (const float*)d_in[6];   // (B, N)
    const float* e      = (const float*)d_in[7];   // (B, M)
    const float* a      = (const float*)d_in[8];   // (B, M)

    float* out      = (float*)d_out;
    float* out_read = out;                             // (B, M)
    float* out_mem  = out + Bc * Mc;                   // (B, N, M)
    float* out_w    = out + Bc * Mc + (size_t)Bc * Nc * Mc;  // (B, N)

    // Pass A: dots + norms (one warp per row-pair, 8 warps/block)
    sim_kernel<<<(Bc * Nc) / 16, 256>>>((const float4*)memory, (const float4*)k);

    // Pass B: weights + zero-init read accumulator (tiny)
    weight_kernel<<<Bc, Nc>>>(k, beta, g, s, gamma, w_prev, out_w,
                              (float4*)out_read);

    // Pass C: erase/add + read accumulation, split over N for MLP
    dim3 grid3(NSPLIT, Bc);
    write_kernel<<<grid3, 256>>>((const float4*)memory, (const float4*)e,
                                 (const float4*)a, out_w,
                                 (float4*)out_mem, out_read);
}

// round 9
// speedup vs baseline: 1.7289x; 1.0005x over previous
#include <cuda_runtime.h>

#define Bc 128
#define Nc 256
#define Mc 1024
#define M4 (Mc/4)          // 256 float4 per row
#define BSTRIDE4 (Nc*M4)   // float4 per batch
#define NSPLIT 8
#define NCHUNK (Nc/NSPLIT) // 32 rows per split

// Scratch (allocation-free per harness rules)
__device__ float g_dot[Bc*Nc];
__device__ float g_msq[Bc*Nc];

// ---------------------------------------------------------------------------
// Kernel 1: per-(b,n) dot(memory_row, k) and ||memory_row||^2.
// One warp per row. All 8 row-float4s loaded into registers FIRST
// (8 back-to-back independent LDG.128 -> MLP_p1=8), then k (L1-resident,
// shared by all 8 warps of the block) is folded in.
// ---------------------------------------------------------------------------
__global__ void sim_kernel(const float4* __restrict__ mem,
                           const float4* __restrict__ k) {
    int warp = threadIdx.x >> 5;
    int lane = threadIdx.x & 31;
    int row  = blockIdx.x * 8 + warp;          // 0 .. B*N-1
    int b    = row >> 8;

    const float4* mr = mem + (size_t)row * M4;
    const float4* kr = k + b * M4;

    // Batch-load the whole row slice: 8 independent LDG.128 in flight.
    float4 m[8];
#pragma unroll
    for (int j = 0; j < 8; j++) m[j] = mr[lane + j * 32];

    float dot = 0.f, msq = 0.f;
#pragma unroll
    for (int j = 0; j < 8; j++) {
        float4 k4 = kr[lane + j * 32];
        dot += m[j].x * k4.x + m[j].y * k4.y + m[j].z * k4.z + m[j].w * k4.w;
        msq += m[j].x * m[j].x + m[j].y * m[j].y + m[j].z * m[j].z + m[j].w * m[j].w;
    }
#pragma unroll
    for (int o = 16; o > 0; o >>= 1) {
        dot += __shfl_xor_sync(0xFFFFFFFFu, dot, o);
        msq += __shfl_xor_sync(0xFFFFFFFFu, msq, o);
    }
    if (lane == 0) {
        g_dot[row] = dot;
        g_msq[row] = msq;
    }
}

// ---------------------------------------------------------------------------
// Block reductions (256 threads = 8 warps)
// ---------------------------------------------------------------------------
__device__ __forceinline__ float block_reduce_sum(float v, float* sm) {
#pragma unroll
    for (int o = 16; o > 0; o >>= 1) v += __shfl_xor_sync(0xFFFFFFFFu, v, o);
    int warp = threadIdx.x >> 5, lane = threadIdx.x & 31;
    if (lane == 0) sm[warp] = v;
    __syncthreads();
    if (warp == 0) {
        v = (lane < 8) ? sm[lane] : 0.f;
#pragma unroll
        for (int o = 4; o > 0; o >>= 1) v += __shfl_xor_sync(0xFFFFFFFFu, v, o);
        if (lane == 0) sm[0] = v;
    }
    __syncthreads();
    v = sm[0];
    __syncthreads();
    return v;
}

__device__ __forceinline__ float block_reduce_max(float v, float* sm) {
#pragma unroll
    for (int o = 16; o > 0; o >>= 1) v = fmaxf(v, __shfl_xor_sync(0xFFFFFFFFu, v, o));
    int warp = threadIdx.x >> 5, lane = threadIdx.x & 31;
    if (lane == 0) sm[warp] = v;
    __syncthreads();
    if (warp == 0) {
        v = (lane < 8) ? sm[lane] : -3.4e38f;
#pragma unroll
        for (int o = 4; o > 0; o >>= 1) v = fmaxf(v, __shfl_xor_sync(0xFFFFFFFFu, v, o));
        if (lane == 0) sm[0] = v;
    }
    __syncthreads();
    v = sm[0];
    __syncthreads();
    return v;
}

// ---------------------------------------------------------------------------
// Kernel 2: per-b weight pipeline + zero-init of the read output for this b
// (write_kernel accumulates into it atomically afterwards).
// ---------------------------------------------------------------------------
__global__ void weight_kernel(const float* __restrict__ k,
                              const float* __restrict__ beta,
                              const float* __restrict__ g,
                              const float* __restrict__ s,
                              const float* __restrict__ gamma,
                              const float* __restrict__ w_prev,
                              float* __restrict__ w_out,
                              float4* __restrict__ read_out) {
    int b = blockIdx.x;
    int n = threadIdx.x;

    // zero the read accumulator for this batch (1 float4 per thread)
    read_out[b * M4 + n] = make_float4(0.f, 0.f, 0.f, 0.f);

    __shared__ float sred[32];
    __shared__ float sw[Nc];

    const float* kb = k + b * Mc;
    float kq = 0.f;
#pragma unroll
    for (int j = 0; j < 4; j++) {
        float v = kb[n + j * 256];
        kq += v * v;
    }
    kq = block_reduce_sum(kq, sred);
    float knorm = fmaxf(sqrtf(kq), 1e-8f);

    float mnorm = fmaxf(sqrtf(g_msq[b * Nc + n]), 1e-8f);
    float cosv  = g_dot[b * Nc + n] / (mnorm * knorm);

    float x    = beta[b] * cosv;
    float xmax = block_reduce_max(x, sred);
    float p    = expf(x - xmax);
    float psum = block_reduce_sum(p, sred);
    float wc   = p / psum;

    float gg = g[b];
    float wg = gg * wc + (1.f - gg) * w_prev[b * Nc + n];
    sw[n] = wg;
    __syncthreads();

    float s0 = s[b * 3 + 0], s1 = s[b * 3 + 1], s2 = s[b * 3 + 2];
    float wt = s0 * sw[(n + Nc - 1) & (Nc - 1)]
             + s1 * sw[n]
             + s2 * sw[(n + 1) & (Nc - 1)];

    float wp   = powf(wt, gamma[b]);
    float wsum = block_reduce_sum(wp, sred);
    w_out[b * Nc + n] = wp / (wsum + 1e-16f);
}

// ---------------------------------------------------------------------------
// Kernel 3: erase/add write + read accumulation. Grid (NSPLIT, B), 256 thr.
// Thread t owns float4 column t; each block covers NCHUNK=32 rows.
// Read partial goes straight to out_read via REDG atomics (8 contributors
// per address, spread addresses -> negligible vs the 276 MB stream).
// ---------------------------------------------------------------------------
__global__ void write_kernel(const float4* __restrict__ mem,
                             const float4* __restrict__ e,
                             const float4* __restrict__ a,
                             const float*  __restrict__ w,
                             float4* __restrict__ newmem,
                             float* __restrict__ read_out) {
    __shared__ float sw[NCHUNK];
    int sp = blockIdx.x;                 // 0..NSPLIT-1
    int b  = (Bc - 1) - blockIdx.y;      // reversed batch order (L2 tail reuse)
    int t  = threadIdx.x;                // 0..255
    int nbase = sp * NCHUNK;

    if (t < NCHUNK) sw[t] = w[b * Nc + nbase + t];

    float4 e4 = e[b * M4 + t];
    float4 a4 = a[b * M4 + t];
    __syncthreads();

    const float4* mb = mem    + (size_t)b * BSTRIDE4 + (size_t)nbase * M4 + t;
    float4*       nb = newmem + (size_t)b * BSTRIDE4 + (size_t)nbase * M4 + t;

    float4 acc = make_float4(0.f, 0.f, 0.f, 0.f);

#pragma unroll 2
    for (int n0 = NCHUNK - 4; n0 >= 0; n0 -= 4) {
        float4 v0 = mb[(n0 + 3) * M4];
        float4 v1 = mb[(n0 + 2) * M4];
        float4 v2 = mb[(n0 + 1) * M4];
        float4 v3 = mb[(n0 + 0) * M4];
        float w0 = sw[n0 + 3], w1 = sw[n0 + 2], w2 = sw[n0 + 1], w3 = sw[n0 + 0];

        float4 r;
        r.x = v0.x * (1.f - w0 * e4.x) + w0 * a4.x;
        r.y = v0.y * (1.f - w0 * e4.y) + w0 * a4.y;
        r.z = v0.z * (1.f - w0 * e4.z) + w0 * a4.z;
        r.w = v0.w * (1.f - w0 * e4.w) + w0 * a4.w;
        nb[(n0 + 3) * M4] = r;
        acc.x += w0 * r.x; acc.y += w0 * r.y; acc.z += w0 * r.z; acc.w += w0 * r.w;

        r.x = v1.x * (1.f - w1 * e4.x) + w1 * a4.x;
        r.y = v1.y * (1.f - w1 * e4.y) + w1 * a4.y;
        r.z = v1.z * (1.f - w1 * e4.z) + w1 * a4.z;
        r.w = v1.w * (1.f - w1 * e4.w) + w1 * a4.w;
        nb[(n0 + 2) * M4] = r;
        acc.x += w1 * r.x; acc.y += w1 * r.y; acc.z += w1 * r.z; acc.w += w1 * r.w;

        r.x = v2.x * (1.f - w2 * e4.x) + w2 * a4.x;
        r.y = v2.y * (1.f - w2 * e4.y) + w2 * a4.y;
        r.z = v2.z * (1.f - w2 * e4.z) + w2 * a4.z;
        r.w = v2.w * (1.f - w2 * e4.w) + w2 * a4.w;
        nb[(n0 + 1) * M4] = r;
        acc.x += w2 * r.x; acc.y += w2 * r.y; acc.z += w2 * r.z; acc.w += w2 * r.w;

        r.x = v3.x * (1.f - w3 * e4.x) + w3 * a4.x;
        r.y = v3.y * (1.f - w3 * e4.y) + w3 * a4.y;
        r.z = v3.z * (1.f - w3 * e4.z) + w3 * a4.z;
        r.w = v3.w * (1.f - w3 * e4.w) + w3 * a4.w;
        nb[(n0 + 0) * M4] = r;
        acc.x += w3 * r.x; acc.y += w3 * r.y; acc.z += w3 * r.z; acc.w += w3 * r.w;
    }

    float* ro = read_out + b * Mc + t * 4;
    atomicAdd(ro + 0, acc.x);
    atomicAdd(ro + 1, acc.y);
    atomicAdd(ro + 2, acc.z);
    atomicAdd(ro + 3, acc.w);
}

// ---------------------------------------------------------------------------
// Launch
// ---------------------------------------------------------------------------
extern "C" void kernel_launch(void* const* d_in, const int* in_sizes, int n_in,
                              void* d_out, int out_size) {
    const float* memory = (const float*)d_in[0];   // (B, N, M)
    const float* k      = (const float*)d_in[1];   // (B, M)
    const float* beta   = (const float*)d_in[2];   // (B, 1)
    const float* g      = (const float*)d_in[3];   // (B, 1)
    const float* s      = (const float*)d_in[4];   // (B, 3)
    const float* gamma  = (const float*)d_in[5];   // (B, 1)
    const float* w_prev = (const float*)d_in[6];   // (B, N)
    const float* e      = (const float*)d_in[7];   // (B, M)
    const float* a      = (const float*)d_in[8];   // (B, M)

    float* out      = (float*)d_out;
    float* out_read = out;                             // (B, M)
    float* out_mem  = out + Bc * Mc;                   // (B, N, M)
    float* out_w    = out + Bc * Mc + (size_t)Bc * Nc * Mc;  // (B, N)

    // Pass A: dots + norms (one warp per row, batched loads, 8 warps/block)
    sim_kernel<<<(Bc * Nc) / 8, 256>>>((const float4*)memory, (const float4*)k);

    // Pass B: weights + zero-init read accumulator (tiny)
    weight_kernel<<<Bc, Nc>>>(k, beta, g, s, gamma, w_prev, out_w,
                              (float4*)out_read);

    // Pass C: erase/add + read accumulation, split over N for MLP
    dim3 grid3(NSPLIT, Bc);
    write_kernel<<<grid3, 256>>>((const float4*)memory, (const float4*)e,
                                 (const float4*)a, out_w,
                                 (float4*)out_mem, out_read);
}

// round 13
// speedup vs baseline: 1.7376x; 1.0050x over previous
#include <cuda_runtime.h>

#define Bc 128
#define Nc 256
#define Mc 1024
#define M4 (Mc/4)          // 256 float4 per row
#define BSTRIDE4 (Nc*M4)   // float4 per batch
#define NSPLIT 8
#define NCHUNK (Nc/NSPLIT) // 32 rows per split

// Scratch (allocation-free per harness rules)
__device__ float g_dot[Bc*Nc];
__device__ float g_msq[Bc*Nc];

// ---------------------------------------------------------------------------
// Kernel 1: per-(b,n) dot(memory_row, k) and ||memory_row||^2.
// One warp per row, 4 warps/block (measured-best config). Blocks 0..127
// additionally zero the read accumulator (write_kernel atomically adds).
// ---------------------------------------------------------------------------
__global__ void sim_kernel(const float4* __restrict__ mem,
                           const float4* __restrict__ k,
                           float4* __restrict__ read_out) {
    // zero-init read accumulator: 128 blocks x 128 threads x 2 float4
    if (blockIdx.x < Bc) {
        int base = blockIdx.x * M4 + threadIdx.x;
        read_out[base]       = make_float4(0.f, 0.f, 0.f, 0.f);
        read_out[base + 128] = make_float4(0.f, 0.f, 0.f, 0.f);
    }

    int warp = threadIdx.x >> 5;
    int lane = threadIdx.x & 31;
    int row  = blockIdx.x * 4 + warp;          // 0 .. B*N-1
    int b    = row >> 8;

    const float4* mr = mem + (size_t)row * M4;
    const float4* kr = k + b * M4;

    float dot = 0.f, msq = 0.f;
#pragma unroll
    for (int j = 0; j < 8; j++) {
        int i = lane + j * 32;
        float4 m4 = mr[i];
        float4 k4 = kr[i];
        dot += m4.x * k4.x + m4.y * k4.y + m4.z * k4.z + m4.w * k4.w;
        msq += m4.x * m4.x + m4.y * m4.y + m4.z * m4.z + m4.w * m4.w;
    }
#pragma unroll
    for (int o = 16; o > 0; o >>= 1) {
        dot += __shfl_xor_sync(0xFFFFFFFFu, dot, o);
        msq += __shfl_xor_sync(0xFFFFFFFFu, msq, o);
    }
    if (lane == 0) {
        g_dot[row] = dot;
        g_msq[row] = msq;
    }
}

// ---------------------------------------------------------------------------
// Block reductions (256 threads = 8 warps)
// ---------------------------------------------------------------------------
__device__ __forceinline__ float block_reduce_sum(float v, float* sm) {
#pragma unroll
    for (int o = 16; o > 0; o >>= 1) v += __shfl_xor_sync(0xFFFFFFFFu, v, o);
    int warp = threadIdx.x >> 5, lane = threadIdx.x & 31;
    if (lane == 0) sm[warp] = v;
    __syncthreads();
    if (warp == 0) {
        v = (lane < 8) ? sm[lane] : 0.f;
#pragma unroll
        for (int o = 4; o > 0; o >>= 1) v += __shfl_xor_sync(0xFFFFFFFFu, v, o);
        if (lane == 0) sm[0] = v;
    }
    __syncthreads();
    v = sm[0];
    __syncthreads();
    return v;
}

__device__ __forceinline__ float block_reduce_max(float v, float* sm) {
#pragma unroll
    for (int o = 16; o > 0; o >>= 1) v = fmaxf(v, __shfl_xor_sync(0xFFFFFFFFu, v, o));
    int warp = threadIdx.x >> 5, lane = threadIdx.x & 31;
    if (lane == 0) sm[warp] = v;
    __syncthreads();
    if (warp == 0) {
        v = (lane < 8) ? sm[lane] : -3.4e38f;
#pragma unroll
        for (int o = 4; o > 0; o >>= 1) v = fmaxf(v, __shfl_xor_sync(0xFFFFFFFFu, v, o));
        if (lane == 0) sm[0] = v;
    }
    __syncthreads();
    v = sm[0];
    __syncthreads();
    return v;
}

// ---------------------------------------------------------------------------
// Kernel 2 (fused): weight pipeline preamble (redundant per sp, hidden under
// co-resident blocks' streaming) + erase/add write + atomic read fold.
// Grid (NSPLIT, B), 256 threads. Thread t owns float4 column t.
// ---------------------------------------------------------------------------
__global__ void write_kernel(const float4* __restrict__ mem,
                             const float4* __restrict__ e,
                             const float4* __restrict__ a,
                             const float*  __restrict__ k,
                             const float*  __restrict__ beta,
                             const float*  __restrict__ g,
                             const float*  __restrict__ s,
                             const float*  __restrict__ gamma,
                             const float*  __restrict__ w_prev,
                             float* __restrict__ w_out,
                             float4* __restrict__ newmem,
                             float* __restrict__ read_out) {
    __shared__ float sred[32];
    __shared__ float sw[Nc];

    int sp = blockIdx.x;                 // 0..NSPLIT-1
    int b  = (Bc - 1) - blockIdx.y;      // reversed batch order (L2 tail reuse)
    int t  = threadIdx.x;                // 0..255 (also n index for weights)
    int nbase = sp * NCHUNK;

    // Issue the streaming operand loads early (overlap with weight preamble)
    float4 e4 = e[b * M4 + t];
    float4 a4 = a[b * M4 + t];

    // ---- weight pipeline (redundant across sp; deterministic) ----
    const float* kb = k + b * Mc;
    float kq = 0.f;
#pragma unroll
    for (int j = 0; j < 4; j++) {
        float v = kb[t + j * 256];
        kq += v * v;
    }
    kq = block_reduce_sum(kq, sred);
    float knorm = fmaxf(sqrtf(kq), 1e-8f);

    float mnorm = fmaxf(sqrtf(g_msq[b * Nc + t]), 1e-8f);
    float cosv  = g_dot[b * Nc + t] / (mnorm * knorm);

    float x    = beta[b] * cosv;
    float xmax = block_reduce_max(x, sred);
    float p    = expf(x - xmax);
    float psum = block_reduce_sum(p, sred);
    float wc   = p / psum;

    float gg = g[b];
    float wg = gg * wc + (1.f - gg) * w_prev[b * Nc + t];
    sw[t] = wg;
    __syncthreads();

    float s0 = s[b * 3 + 0], s1 = s[b * 3 + 1], s2 = s[b * 3 + 2];
    float wt = s0 * sw[(t + Nc - 1) & (Nc - 1)]
             + s1 * sw[t]
             + s2 * sw[(t + 1) & (Nc - 1)];

    float wp   = powf(wt, gamma[b]);
    float wsum = block_reduce_sum(wp, sred);
    float wfin = wp / (wsum + 1e-16f);

    if (sp == 0) w_out[b * Nc + t] = wfin;   // emit w output once per b

    __syncthreads();          // all taps/reduce reads of sw done
    sw[t] = wfin;
    __syncthreads();

    // ---- streaming erase/add + read fold ----
    const float4* mb = mem    + (size_t)b * BSTRIDE4 + (size_t)nbase * M4 + t;
    float4*       nb = newmem + (size_t)b * BSTRIDE4 + (size_t)nbase * M4 + t;

    float4 acc = make_float4(0.f, 0.f, 0.f, 0.f);

#pragma unroll 2
    for (int n0 = NCHUNK - 4; n0 >= 0; n0 -= 4) {
        float4 v0 = mb[(n0 + 3) * M4];
        float4 v1 = mb[(n0 + 2) * M4];
        float4 v2 = mb[(n0 + 1) * M4];
        float4 v3 = mb[(n0 + 0) * M4];
        float w0 = sw[nbase + n0 + 3], w1 = sw[nbase + n0 + 2];
        float w2 = sw[nbase + n0 + 1], w3 = sw[nbase + n0 + 0];

        float4 r;
        r.x = v0.x * (1.f - w0 * e4.x) + w0 * a4.x;
        r.y = v0.y * (1.f - w0 * e4.y) + w0 * a4.y;
        r.z = v0.z * (1.f - w0 * e4.z) + w0 * a4.z;
        r.w = v0.w * (1.f - w0 * e4.w) + w0 * a4.w;
        nb[(n0 + 3) * M4] = r;
        acc.x += w0 * r.x; acc.y += w0 * r.y; acc.z += w0 * r.z; acc.w += w0 * r.w;

        r.x = v1.x * (1.f - w1 * e4.x) + w1 * a4.x;
        r.y = v1.y * (1.f - w1 * e4.y) + w1 * a4.y;
        r.z = v1.z * (1.f - w1 * e4.z) + w1 * a4.z;
        r.w = v1.w * (1.f - w1 * e4.w) + w1 * a4.w;
        nb[(n0 + 2) * M4] = r;
        acc.x += w1 * r.x; acc.y += w1 * r.y; acc.z += w1 * r.z; acc.w += w1 * r.w;

        r.x = v2.x * (1.f - w2 * e4.x) + w2 * a4.x;
        r.y = v2.y * (1.f - w2 * e4.y) + w2 * a4.y;
        r.z = v2.z * (1.f - w2 * e4.z) + w2 * a4.z;
        r.w = v2.w * (1.f - w2 * e4.w) + w2 * a4.w;
        nb[(n0 + 1) * M4] = r;
        acc.x += w2 * r.x; acc.y += w2 * r.y; acc.z += w2 * r.z; acc.w += w2 * r.w;

        r.x = v3.x * (1.f - w3 * e4.x) + w3 * a4.x;
        r.y = v3.y * (1.f - w3 * e4.y) + w3 * a4.y;
        r.z = v3.z * (1.f - w3 * e4.z) + w3 * a4.z;
        r.w = v3.w * (1.f - w3 * e4.w) + w3 * a4.w;
        nb[(n0 + 0) * M4] = r;
        acc.x += w3 * r.x; acc.y += w3 * r.y; acc.z += w3 * r.z; acc.w += w3 * r.w;
    }

    float* ro = read_out + b * Mc + t * 4;
    atomicAdd(ro + 0, acc.x);
    atomicAdd(ro + 1, acc.y);
    atomicAdd(ro + 2, acc.z);
    atomicAdd(ro + 3, acc.w);
}

// ---------------------------------------------------------------------------
// Launch
// ---------------------------------------------------------------------------
extern "C" void kernel_launch(void* const* d_in, const int* in_sizes, int n_in,
                              void* d_out, int out_size) {
    const float* memory = (const float*)d_in[0];   // (B, N, M)
    const float* k      = (const float*)d_in[1];   // (B, M)
    const float* beta   = (const float*)d_in[2];   // (B, 1)
    const float* g      = (const float*)d_in[3];   // (B, 1)
    const float* s      = (const float*)d_in[4];   // (B, 3)
    const float* gamma  = (const float*)d_in[5];   // (B, 1)
    const float* w_prev = (const float*)d_in[6];   // (B, N)
    const float* e      = (const float*)d_in[7];   // (B, M)
    const float* a      = (const float*)d_in[8];   // (B, M)

    float* out      = (float*)d_out;
    float* out_read = out;                             // (B, M)
    float* out_mem  = out + Bc * Mc;                   // (B, N, M)
    float* out_w    = out + Bc * Mc + (size_t)Bc * Nc * Mc;  // (B, N)

    // Pass A: dots + norms + read_out zero-init (one warp per row)
    sim_kernel<<<(Bc * Nc) / 4, 128>>>((const float4*)memory, (const float4*)k,
                                       (float4*)out_read);

    // Pass B (fused): weights + erase/add + read fold
    dim3 grid2(NSPLIT, Bc);
    write_kernel<<<grid2, 256>>>((const float4*)memory, (const float4*)e,
                                 (const float4*)a, k, beta, g, s, gamma,
                                 w_prev, out_w, (float4*)out_mem, out_read);
}

// round 14
// speedup vs baseline: 1.8353x; 1.0562x over previous
#include <cuda_runtime.h>

#define Bc 128
#define Nc 256
#define Mc 1024
#define M4 (Mc/4)          // 256 float4 per row
#define BSTRIDE4 (Nc*M4)   // float4 per batch
#define NSPLIT 8
#define NCHUNK (Nc/NSPLIT) // 32 rows per split

// Scratch (allocation-free per harness rules)
__device__ float g_dot[Bc*Nc];
__device__ float g_msq[Bc*Nc];

// ---------------------------------------------------------------------------
// Kernel 1: per-(b,n) dot(memory_row, k) and ||memory_row||^2.
// One warp per row, 4 warps/block. Default (allocating) loads on memory:
// this pass doubles as the L2 prefetch for the write pass. Blocks 0..127
// also zero the read accumulator.
// ---------------------------------------------------------------------------
__global__ void sim_kernel(const float4* __restrict__ mem,
                           const float4* __restrict__ k,
                           float4* __restrict__ read_out) {
    if (blockIdx.x < Bc) {
        int base = blockIdx.x * M4 + threadIdx.x;
        read_out[base]       = make_float4(0.f, 0.f, 0.f, 0.f);
        read_out[base + 128] = make_float4(0.f, 0.f, 0.f, 0.f);
    }

    int warp = threadIdx.x >> 5;
    int lane = threadIdx.x & 31;
    int row  = blockIdx.x * 4 + warp;          // 0 .. B*N-1
    int b    = row >> 8;

    const float4* mr = mem + (size_t)row * M4;
    const float4* kr = k + b * M4;

    float dot = 0.f, msq = 0.f;
#pragma unroll
    for (int j = 0; j < 8; j++) {
        int i = lane + j * 32;
        float4 m4 = mr[i];
        float4 k4 = kr[i];
        dot += m4.x * k4.x + m4.y * k4.y + m4.z * k4.z + m4.w * k4.w;
        msq += m4.x * m4.x + m4.y * m4.y + m4.z * m4.z + m4.w * m4.w;
    }
#pragma unroll
    for (int o = 16; o > 0; o >>= 1) {
        dot += __shfl_xor_sync(0xFFFFFFFFu, dot, o);
        msq += __shfl_xor_sync(0xFFFFFFFFu, msq, o);
    }
    if (lane == 0) {
        g_dot[row] = dot;
        g_msq[row] = msq;
    }
}

// ---------------------------------------------------------------------------
// Block reductions (256 threads = 8 warps)
// ---------------------------------------------------------------------------
__device__ __forceinline__ float block_reduce_sum(float v, float* sm) {
#pragma unroll
    for (int o = 16; o > 0; o >>= 1) v += __shfl_xor_sync(0xFFFFFFFFu, v, o);
    int warp = threadIdx.x >> 5, lane = threadIdx.x & 31;
    if (lane == 0) sm[warp] = v;
    __syncthreads();
    if (warp == 0) {
        v = (lane < 8) ? sm[lane] : 0.f;
#pragma unroll
        for (int o = 4; o > 0; o >>= 1) v += __shfl_xor_sync(0xFFFFFFFFu, v, o);
        if (lane == 0) sm[0] = v;
    }
    __syncthreads();
    v = sm[0];
    __syncthreads();
    return v;
}

__device__ __forceinline__ float block_reduce_max(float v, float* sm) {
#pragma unroll
    for (int o = 16; o > 0; o >>= 1) v = fmaxf(v, __shfl_xor_sync(0xFFFFFFFFu, v, o));
    int warp = threadIdx.x >> 5, lane = threadIdx.x & 31;
    if (lane == 0) sm[warp] = v;
    __syncthreads();
    if (warp == 0) {
        v = (lane < 8) ? sm[lane] : -3.4e38f;
#pragma unroll
        for (int o = 4; o > 0; o >>= 1) v = fmaxf(v, __shfl_xor_sync(0xFFFFFFFFu, v, o));
        if (lane == 0) sm[0] = v;
    }
    __syncthreads();
    v = sm[0];
    __syncthreads();
    return v;
}

// ---------------------------------------------------------------------------
// Kernel 2 (fused): weight pipeline preamble + erase/add write + atomic read
// fold. Grid (NSPLIT, B), 256 threads.
// Cache policy: memory read = __ldlu (last-use: line dies after read),
// newmem store = __stcs (evict-first: never re-read, don't pollute L2).
// This preserves the L2 footprint sim_kernel left behind.
// ---------------------------------------------------------------------------
__global__ void write_kernel(const float4* __restrict__ mem,
                             const float4* __restrict__ e,
                             const float4* __restrict__ a,
                             const float*  __restrict__ k,
                             const float*  __restrict__ beta,
                             const float*  __restrict__ g,
                             const float*  __restrict__ s,
                             const float*  __restrict__ gamma,
                             const float*  __restrict__ w_prev,
                             float* __restrict__ w_out,
                             float4* __restrict__ newmem,
                             float* __restrict__ read_out) {
    __shared__ float sred[32];
    __shared__ float sw[Nc];

    int sp = blockIdx.x;                 // 0..NSPLIT-1
    int b  = (Bc - 1) - blockIdx.y;      // reversed batch order (L2 tail reuse)
    int t  = threadIdx.x;                // 0..255 (also n index for weights)
    int nbase = sp * NCHUNK;

    // Issue the streaming operand loads early (overlap with weight preamble)
    float4 e4 = e[b * M4 + t];
    float4 a4 = a[b * M4 + t];

    // ---- weight pipeline (redundant across sp; deterministic) ----
    const float* kb = k + b * Mc;
    float kq = 0.f;
#pragma unroll
    for (int j = 0; j < 4; j++) {
        float v = kb[t + j * 256];
        kq += v * v;
    }
    kq = block_reduce_sum(kq, sred);
    float knorm = fmaxf(sqrtf(kq), 1e-8f);

    float mnorm = fmaxf(sqrtf(g_msq[b * Nc + t]), 1e-8f);
    float cosv  = g_dot[b * Nc + t] / (mnorm * knorm);

    float x    = beta[b] * cosv;
    float xmax = block_reduce_max(x, sred);
    float p    = expf(x - xmax);
    float psum = block_reduce_sum(p, sred);
    float wc   = p / psum;

    float gg = g[b];
    float wg = gg * wc + (1.f - gg) * w_prev[b * Nc + t];
    sw[t] = wg;
    __syncthreads();

    float s0 = s[b * 3 + 0], s1 = s[b * 3 + 1], s2 = s[b * 3 + 2];
    float wt = s0 * sw[(t + Nc - 1) & (Nc - 1)]
             + s1 * sw[t]
             + s2 * sw[(t + 1) & (Nc - 1)];

    float wp   = powf(wt, gamma[b]);
    float wsum = block_reduce_sum(wp, sred);
    float wfin = wp / (wsum + 1e-16f);

    if (sp == 0) w_out[b * Nc + t] = wfin;   // emit w output once per b

    __syncthreads();          // all taps/reduce reads of sw done
    sw[t] = wfin;
    __syncthreads();

    // ---- streaming erase/add + read fold ----
    const float4* mb = mem    + (size_t)b * BSTRIDE4 + (size_t)nbase * M4 + t;
    float4*       nb = newmem + (size_t)b * BSTRIDE4 + (size_t)nbase * M4 + t;

    float4 acc = make_float4(0.f, 0.f, 0.f, 0.f);

#pragma unroll 2
    for (int n0 = NCHUNK - 4; n0 >= 0; n0 -= 4) {
        float4 v0 = __ldlu(&mb[(n0 + 3) * M4]);
        float4 v1 = __ldlu(&mb[(n0 + 2) * M4]);
        float4 v2 = __ldlu(&mb[(n0 + 1) * M4]);
        float4 v3 = __ldlu(&mb[(n0 + 0) * M4]);
        float w0 = sw[nbase + n0 + 3], w1 = sw[nbase + n0 + 2];
        float w2 = sw[nbase + n0 + 1], w3 = sw[nbase + n0 + 0];

        float4 r;
        r.x = v0.x * (1.f - w0 * e4.x) + w0 * a4.x;
        r.y = v0.y * (1.f - w0 * e4.y) + w0 * a4.y;
        r.z = v0.z * (1.f - w0 * e4.z) + w0 * a4.z;
        r.w = v0.w * (1.f - w0 * e4.w) + w0 * a4.w;
        __stcs(&nb[(n0 + 3) * M4], r);
        acc.x += w0 * r.x; acc.y += w0 * r.y; acc.z += w0 * r.z; acc.w += w0 * r.w;

        r.x = v1.x * (1.f - w1 * e4.x) + w1 * a4.x;
        r.y = v1.y * (1.f - w1 * e4.y) + w1 * a4.y;
        r.z = v1.z * (1.f - w1 * e4.z) + w1 * a4.z;
        r.w = v1.w * (1.f - w1 * e4.w) + w1 * a4.w;
        __stcs(&nb[(n0 + 2) * M4], r);
        acc.x += w1 * r.x; acc.y += w1 * r.y; acc.z += w1 * r.z; acc.w += w1 * r.w;

        r.x = v2.x * (1.f - w2 * e4.x) + w2 * a4.x;
        r.y = v2.y * (1.f - w2 * e4.y) + w2 * a4.y;
        r.z = v2.z * (1.f - w2 * e4.z) + w2 * a4.z;
        r.w = v2.w * (1.f - w2 * e4.w) + w2 * a4.w;
        __stcs(&nb[(n0 + 1) * M4], r);
        acc.x += w2 * r.x; acc.y += w2 * r.y; acc.z += w2 * r.z; acc.w += w2 * r.w;

        r.x = v3.x * (1.f - w3 * e4.x) + w3 * a4.x;
        r.y = v3.y * (1.f - w3 * e4.y) + w3 * a4.y;
        r.z = v3.z * (1.f - w3 * e4.z) + w3 * a4.z;
        r.w = v3.w * (1.f - w3 * e4.w) + w3 * a4.w;
        __stcs(&nb[(n0 + 0) * M4], r);
        acc.x += w3 * r.x; acc.y += w3 * r.y; acc.z += w3 * r.z; acc.w += w3 * r.w;
    }

    float* ro = read_out + b * Mc + t * 4;
    atomicAdd(ro + 0, acc.x);
    atomicAdd(ro + 1, acc.y);
    atomicAdd(ro + 2, acc.z);
    atomicAdd(ro + 3, acc.w);
}

// ---------------------------------------------------------------------------
// Launch
// ---------------------------------------------------------------------------
extern "C" void kernel_launch(void* const* d_in, const int* in_sizes, int n_in,
                              void* d_out, int out_size) {
    const float* memory = (const float*)d_in[0];   // (B, N, M)
    const float* k      = (const float*)d_in[1];   // (B, M)
    const float* beta   = (const float*)d_in[2];   // (B, 1)
    const float* g      = (const float*)d_in[3];   // (B, 1)
    const float* s      = (const float*)d_in[4];   // (B, 3)
    const float* gamma  = (const float*)d_in[5];   // (B, 1)
    const float* w_prev = (const float*)d_in[6];   // (B, N)
    const float* e      = (const float*)d_in[7];   // (B, M)
    const float* a      = (const float*)d_in[8];   // (B, M)

    float* out      = (float*)d_out;
    float* out_read = out;                             // (B, M)
    float* out_mem  = out + Bc * Mc;                   // (B, N, M)
    float* out_w    = out + Bc * Mc + (size_t)Bc * Nc * Mc;  // (B, N)

    // Pass A: dots + norms + read_out zero-init (one warp per row)
    sim_kernel<<<(Bc * Nc) / 4, 128>>>((const float4*)memory, (const float4*)k,
                                       (float4*)out_read);

    // Pass B (fused): weights + erase/add + read fold (cache-controlled)
    dim3 grid2(NSPLIT, Bc);
    write_kernel<<<grid2, 256>>>((const float4*)memory, (const float4*)e,
                                 (const float4*)a, k, beta, g, s, gamma,
                                 w_prev, out_w, (float4*)out_mem, out_read);
}